// round 9
// baseline (speedup 1.0000x reference)
#include <cuda_runtime.h>
#include <cuda_bf16.h>

#define NB 64
#define TT 512
#define II 512
#define HH 1024
#define OO 512
#define NT (NB*TT)
#define NHh (NB*HH)

__device__ float g_bufA[TT*NB*HH];
__device__ float g_bufB[TT*NB*HH];
__device__ float g_bufO[NT*OO];
__device__ float g_bufO2[NT*OO];
__device__ float g_hx0[HH*NB];
__device__ float g_hx1[HH*NB];
__device__ unsigned g_gflag[32*32];   // recur slice flags [half][group]
__device__ unsigned g_done[2*32];     // recur step counters per half (+64/step)
__device__ unsigned g_g1slab[4*32];   // G1 tiles done per t-slab (tgt 1024)
__device__ unsigned g_g3slab[4*32];   // G3 per slab (tgt 512)
__device__ unsigned g_g4slab[4*32];   // G4 per slab (tgt 512)

__device__ __forceinline__ unsigned long long dup2(float a) {
    unsigned long long r; asm("mov.b64 %0, {%1, %1};" : "=l"(r) : "f"(a)); return r;
}
__device__ __forceinline__ void fma2(unsigned long long& c, unsigned long long a,
                                     unsigned long long b) {
    asm("fma.rn.f32x2 %0, %1, %2, %0;" : "+l"(c) : "l"(a), "l"(b));
}
__device__ __forceinline__ float lo32(unsigned long long v) {
    return __uint_as_float((unsigned)(v & 0xffffffffull));
}
__device__ __forceinline__ float hi32(unsigned long long v) {
    return __uint_as_float((unsigned)(v >> 32));
}
__device__ __forceinline__ unsigned ld_acq(const unsigned* p) {
    unsigned v;
    asm volatile("ld.acquire.gpu.global.u32 %0, [%1];" : "=r"(v) : "l"(p));
    return v;
}
__device__ __forceinline__ void red_rel(unsigned* p, unsigned v) {
    asm volatile("red.add.release.gpu.global.u32 [%0], %1;" :: "l"(p), "r"(v));
}
__device__ __forceinline__ float retanh(float x) {
    float xm = fmaxf(x, 0.0f);
    float e;
    asm("ex2.approx.f32 %0, %1;" : "=f"(e) : "f"(xm * -2.885390082f));
    return __fdividef(1.0f - e, 1.0f + e);
}

// ---------- 512-thread GEMM tile: BM=128, BN=64, 4x4 microtile, dbl-buffered --
#define ASX(b,k,r) As[(b)*2112 + (k)*132 + (r)]
#define BSX(b,k,r) Bs[(b)*1088 + (k)*68 + (r)]
__device__ void gemm512_tile(
    const float* __restrict__ A, const float* __restrict__ B,
    const float* __restrict__ b1, const float* __restrict__ b2,
    float* __restrict__ C, int K, int Nc, int m0, int j0,
    int D1, int D2, int act, float* smem)
{
    float* As = smem;          // [2][16][132]
    float* Bs = smem + 4224;   // [2][16][68]
    const int tid = threadIdx.x;
    const int ar = tid & 127, ac4 = (tid >> 7) * 4;
    const int br = tid >> 3,  bc2 = (tid & 7) * 2;
    const int tmr = tid >> 4, tnc = tid & 15;
    const float* apt = A + (size_t)(m0 + ar) * K + ac4;
    const float* bpt = B + (size_t)(j0 + br) * K + bc2;

    unsigned long long acc[4][2];
#pragma unroll
    for (int i = 0; i < 4; i++) { acc[i][0] = 0ull; acc[i][1] = 0ull; }
    {
        float4 pa = *(const float4*)apt;
        float2 pb = *(const float2*)bpt;
        ASX(0, ac4 + 0, ar) = pa.x; ASX(0, ac4 + 1, ar) = pa.y;
        ASX(0, ac4 + 2, ar) = pa.z; ASX(0, ac4 + 3, ar) = pa.w;
        BSX(0, bc2 + 0, br) = pb.x; BSX(0, bc2 + 1, br) = pb.y;
    }
    __syncthreads();
    int cur = 0;
    for (int kt = 0; kt < K; kt += 16) {
        float4 pa; float2 pb;
        const bool more = (kt + 16 < K);
        if (more) {
            pa = *(const float4*)(apt + kt + 16);
            pb = *(const float2*)(bpt + kt + 16);
        }
#pragma unroll
        for (int kk = 0; kk < 16; kk++) {
            float4 a = *(const float4*)&ASX(cur, kk, tmr * 4);
            ulonglong2 b = *(const ulonglong2*)&BSX(cur, kk, tnc * 4);
            unsigned long long ad;
            ad = dup2(a.x); fma2(acc[0][0], ad, b.x); fma2(acc[0][1], ad, b.y);
            ad = dup2(a.y); fma2(acc[1][0], ad, b.x); fma2(acc[1][1], ad, b.y);
            ad = dup2(a.z); fma2(acc[2][0], ad, b.x); fma2(acc[2][1], ad, b.y);
            ad = dup2(a.w); fma2(acc[3][0], ad, b.x); fma2(acc[3][1], ad, b.y);
        }
        if (more) {
            const int nxt = cur ^ 1;
            ASX(nxt, ac4 + 0, ar) = pa.x; ASX(nxt, ac4 + 1, ar) = pa.y;
            ASX(nxt, ac4 + 2, ar) = pa.z; ASX(nxt, ac4 + 3, ar) = pa.w;
            BSX(nxt, bc2 + 0, br) = pb.x; BSX(nxt, bc2 + 1, br) = pb.y;
            __syncthreads();
            cur = nxt;
        }
    }
    float bc[4];
#pragma unroll
    for (int j = 0; j < 4; j++) {
        const int cn = j0 + tnc * 4 + j;
        float bb = b1[cn];
        if (b2) bb += b2[cn];
        bc[j] = bb;
    }
#pragma unroll
    for (int i = 0; i < 4; i++) {
        const int rm = m0 + tmr * 4 + i;
        const int orow = (rm % D1) * D2 + rm / D1;
        float4 o;
        o.x = lo32(acc[i][0]) + bc[0]; o.y = hi32(acc[i][0]) + bc[1];
        o.z = lo32(acc[i][1]) + bc[2]; o.w = hi32(acc[i][1]) + bc[3];
        if (act) { o.x = retanh(o.x); o.y = retanh(o.y);
                   o.z = retanh(o.z); o.w = retanh(o.w); }
        *(float4*)(C + (size_t)orow * Nc + j0 + tnc * 4) = o;
    }
}

// ---------- recurrence body (512 threads, one batch-half per CTA) -------------
__device__ void recur_body(
    float* __restrict__ buf, const float* __restrict__ Wh,
    float* __restrict__ hx0, float* __restrict__ hx1, int gate, float* smem)
{
    float* Whs = smem;                                                // [1024][16]
    unsigned long long* redU = (unsigned long long*)(smem + 16384);   // [16][32][9]
    const int tid  = threadIdx.x;
    const int bidb = blockIdx.x >> 6;
    const int bidh = blockIdx.x & 63;
    const int nb0  = bidb * 32;
    const int c0   = bidh * 16;
    {
        const int cl = tid & 15;
        const int kb = (tid >> 4) * 32;
        const float* wrow = Wh + (size_t)(c0 + cl) * HH + kb;
#pragma unroll
        for (int kk = 0; kk < 32; kk++) Whs[(kb + kk) * 16 + cl] = wrow[kk];
    }
    __syncthreads();
    const int wid  = tid >> 5;
    const int lane = tid & 31;
    const int k0   = wid * 64;
    const int cR   = lane & 15;
    const int nR   = 2 * wid + (lane >> 4);
    const float* redF = (const float*)redU;
    const unsigned* wf = &g_gflag[(bidb * 16 + wid) * 32];
    unsigned* pf = &g_gflag[(bidb * 16 + (bidh >> 2)) * 32];

    for (int t = 0; t < TT; t++) {
        if (gate && (t & 127) == 0) {       // wait for G1 slab
            if (tid == 0)
                while (ld_acq(&g_g1slab[(t >> 7) * 32]) < 1024u) __nanosleep(40);
            __syncthreads();
        }
        const float* hp = ((t & 1) ? hx1 : hx0) + (size_t)k0 * NB + nb0 + lane;
        float*       hn = ((t & 1) ? hx0 : hx1);
        float* outp = buf + (size_t)t * NHh + (size_t)(nb0 + nR) * HH + (c0 + cR);
        const float x_pre = __ldcg(outp);
        {
            const unsigned tgt = 4u * (unsigned)t;
            while (ld_acq(wf) < tgt) __nanosleep(20);
        }
        unsigned long long acc[8];
#pragma unroll
        for (int j = 0; j < 8; j++) acc[j] = 0ull;
        float hbuf[3][8];
#pragma unroll
        for (int j = 0; j < 8; j++) hbuf[0][j] = __ldcg(hp + (size_t)j * NB);
#pragma unroll
        for (int j = 0; j < 8; j++) hbuf[1][j] = __ldcg(hp + (size_t)(8 + j) * NB);
#pragma unroll
        for (int g = 0; g < 8; g++) {
            if (g + 2 < 8) {
#pragma unroll
                for (int j = 0; j < 8; j++)
                    hbuf[(g + 2) % 3][j] = __ldcg(hp + (size_t)((g + 2) * 8 + j) * NB);
            }
#pragma unroll
            for (int j = 0; j < 8; j++) {
                const unsigned long long ad = dup2(hbuf[g % 3][j]);
                const float* wk = &Whs[(k0 + g * 8 + j) * 16];
                ulonglong2 w0 = *(const ulonglong2*)(wk + 0);
                ulonglong2 w1 = *(const ulonglong2*)(wk + 4);
                ulonglong2 w2 = *(const ulonglong2*)(wk + 8);
                ulonglong2 w3 = *(const ulonglong2*)(wk + 12);
                fma2(acc[0], ad, w0.x); fma2(acc[1], ad, w0.y);
                fma2(acc[2], ad, w1.x); fma2(acc[3], ad, w1.y);
                fma2(acc[4], ad, w2.x); fma2(acc[5], ad, w2.y);
                fma2(acc[6], ad, w3.x); fma2(acc[7], ad, w3.y);
            }
        }
        {
            unsigned long long* rp = &redU[(size_t)(wid * 32 + lane) * 9];
#pragma unroll
            for (int j = 0; j < 8; j++) rp[j] = acc[j];
        }
        __syncthreads();
        float s = 0.0f;
#pragma unroll
        for (int w = 0; w < 16; w++) s += redF[(w * 32 + nR) * 18 + cR];
        const float v = retanh(s + x_pre);
        *outp = v;
        hn[(size_t)(c0 + cR) * NB + nb0 + nR] = v;
        __syncthreads();
        if (tid == 0) {
            red_rel(pf, 1u);
            red_rel(&g_done[bidb * 32], 1u);
        }
    }
}

// ---------- mega kernel: recurrence + gated GEMM roles ------------------------
#define RSMEM ((16384 + 9216) * 4)   // 100 KB

__global__ __launch_bounds__(512, 2) void mega_kernel(
    float* rbuf, const float* rWh, float* hx0, float* hx1, int rgate,
    int nG1, const float* g1A, const float* W1, const float* b1a,
    const float* b1b, float* dst1,
    int nG3, const float* W3, const float* b3, float* dst3,
    int nG4, const float* W4, const float* b4, float* dst4,
    int nG5, const float* W5, const float* b5a, const float* b5b, float* dst5)
{
    extern __shared__ float smem[];
    int bid = blockIdx.x;
    if (bid < 128) { recur_body(rbuf, rWh, hx0, hx1, rgate, smem); return; }
    bid -= 128;
    if (bid < nG1) {              // G1: inp = data@Wi^T (+b), slab-major, no waits
        const int y = bid >> 4, x = bid & 15;
        const int slab = y >> 6, n = y & 63;
        gemm512_tile(g1A, W1, b1a, b1b, dst1, II, HH,
                     n * 512 + slab * 128, x * 64, TT, NB, 0, smem);
        __syncthreads();
        if (threadIdx.x == 0) red_rel(&g_g1slab[slab * 32], 1u);
        return;
    }
    bid -= nG1;
    if (bid < nG3) {              // G3/G7: out = hs@Wo^T + bo, gated per step
        const int y = bid >> 3, x = bid & 7;
        if (threadIdx.x == 0) {
            const unsigned tgt = 64u * (unsigned)(2 * y + 2);
            while (ld_acq(&g_done[0])  < tgt) __nanosleep(100);
            while (ld_acq(&g_done[32]) < tgt) __nanosleep(100);
        }
        __syncthreads();
        gemm512_tile(rbuf, W3, b3, nullptr, dst3, HH, OO, y * 128, x * 64,
                     NB, TT, 0, smem);
        __syncthreads();
        if (threadIdx.x == 0) red_rel(&g_g3slab[(y >> 6) * 32], 1u);
        return;
    }
    bid -= nG3;
    if (bid < nG4) {              // G4: out_t = retanh(out_v@Wt^T + bt)
        const int y = bid >> 3, x = bid & 7;
        const int slab = y >> 6, n = y & 63;
        if (threadIdx.x == 0)
            while (ld_acq(&g_g3slab[slab * 32]) < 512u) __nanosleep(100);
        __syncthreads();
        gemm512_tile(dst3, W4, b4, nullptr, dst4, OO, OO,
                     n * 512 + slab * 128, x * 64, NT, 1, 1, smem);
        __syncthreads();
        if (threadIdx.x == 0) red_rel(&g_g4slab[slab * 32], 1u);
        return;
    }
    bid -= nG4;
    if (bid < nG5) {              // G5: inp_m = out_t@Wi2^T (+b)
        const int y = bid >> 4, x = bid & 15;
        const int slab = y >> 6, n = y & 63;
        if (threadIdx.x == 0)
            while (ld_acq(&g_g4slab[slab * 32]) < 512u) __nanosleep(100);
        __syncthreads();
        gemm512_tile(dst4, W5, b5a, b5b, dst5, OO, HH,
                     n * 512 + slab * 128, x * 64, TT, NB, 0, smem);
    }
}

__global__ __launch_bounds__(512) void transpose_h0(
    const float* __restrict__ h0, float* __restrict__ hx)
{
    const int idx = blockIdx.x * 512 + threadIdx.x;
    hx[idx] = h0[(size_t)(idx & 63) * HH + (idx >> 6)];
}

__global__ __launch_bounds__(1024) void reset_flags_kernel() {
    const int i = threadIdx.x;
    g_gflag[i] = 0u;
    if (i < 64)  g_done[i] = 0u;
    if (i < 128) { g_g1slab[i] = 0u; g_g3slab[i] = 0u; g_g4slab[i] = 0u; }
}

extern "C" void kernel_launch(void* const* d_in, const int* in_sizes, int n_in,
                              void* d_out, int out_size)
{
    const float* data = (const float*)d_in[0];
    const float* h0_v = (const float*)d_in[1];
    const float* h0_m = (const float*)d_in[2];
    const float* Wi   = (const float*)d_in[3];
    const float* bi   = (const float*)d_in[4];
    const float* Wh   = (const float*)d_in[5];
    const float* bh   = (const float*)d_in[6];
    const float* Wo   = (const float*)d_in[7];
    const float* bo   = (const float*)d_in[8];
    const float* Wt   = (const float*)d_in[9];
    const float* bt   = (const float*)d_in[10];
    const float* Wi2  = (const float*)d_in[11];
    const float* bi2  = (const float*)d_in[12];
    const float* Wh2  = (const float*)d_in[13];
    const float* bh2  = (const float*)d_in[14];
    const float* Wo2  = (const float*)d_in[15];
    const float* bo2  = (const float*)d_in[16];
    float* out = (float*)d_out;

    float *bufA, *bufB, *bufO, *bufO2, *hx0, *hx1;
    cudaGetSymbolAddress((void**)&bufA,  g_bufA);
    cudaGetSymbolAddress((void**)&bufB,  g_bufB);
    cudaGetSymbolAddress((void**)&bufO,  g_bufO);
    cudaGetSymbolAddress((void**)&bufO2, g_bufO2);
    cudaGetSymbolAddress((void**)&hx0,   g_hx0);
    cudaGetSymbolAddress((void**)&hx1,   g_hx1);

    cudaFuncSetAttribute(mega_kernel,
                         cudaFuncAttributeMaxDynamicSharedMemorySize, RSMEM);

    // MEGA-A: recur_v + G1(inp_v) + G3(out_v) + G4(out_t) + G5(inp_m)
    transpose_h0<<<128, 512>>>(h0_v, hx0);
    reset_flags_kernel<<<1, 1024>>>();
    mega_kernel<<<128 + 4096 + 2048 + 2048 + 4096, 512, RSMEM>>>(
        bufA, Wh, hx0, hx1, 1,
        4096, data, Wi, bi, bh, bufA,
        2048, Wo, bo, bufO,
        2048, Wt, bt, bufO2,
        4096, Wi2, bi2, bh2, bufB);

    // MEGA-B: recur_m + G7(out_m)
    transpose_h0<<<128, 512>>>(h0_m, hx0);
    reset_flags_kernel<<<1, 1024>>>();
    mega_kernel<<<128 + 2048, 512, RSMEM>>>(
        bufB, Wh2, hx0, hx1, 0,
        0, nullptr, nullptr, nullptr, nullptr, nullptr,
        2048, Wo2, bo2, out,
        0, nullptr, nullptr, nullptr,
        0, nullptr, nullptr, nullptr, nullptr);
}

// round 10
// speedup vs baseline: 1.4123x; 1.4123x over previous
#include <cuda_runtime.h>
#include <cuda_bf16.h>

#define NB 64
#define TT 512
#define II 512
#define HH 1024
#define OO 512
#define NT (NB*TT)
#define NHh (NB*HH)

__device__ float g_bufA[TT*NB*HH];
__device__ float g_bufB[TT*NB*HH];
__device__ float g_bufO[NT*OO];
__device__ float g_bufO2[NT*OO];
__device__ float g_hx0[HH*NB];
__device__ float g_hx1[HH*NB];
__device__ unsigned g_gflag[32*32];   // [half][group] publish counters (64/step)

__device__ __forceinline__ unsigned long long dup2(float a) {
    unsigned long long r; asm("mov.b64 %0, {%1, %1};" : "=l"(r) : "f"(a)); return r;
}
__device__ __forceinline__ void fma2(unsigned long long& c, unsigned long long a,
                                     unsigned long long b) {
    asm("fma.rn.f32x2 %0, %1, %2, %0;" : "+l"(c) : "l"(a), "l"(b));
}
__device__ __forceinline__ float lo32(unsigned long long v) {
    return __uint_as_float((unsigned)(v & 0xffffffffull));
}
__device__ __forceinline__ float hi32(unsigned long long v) {
    return __uint_as_float((unsigned)(v >> 32));
}
__device__ __forceinline__ unsigned ld_acq(const unsigned* p) {
    unsigned v;
    asm volatile("ld.acquire.gpu.global.u32 %0, [%1];" : "=r"(v) : "l"(p));
    return v;
}
__device__ __forceinline__ void red_rel(unsigned* p, unsigned v) {
    asm volatile("red.add.release.gpu.global.u32 [%0], %1;" :: "l"(p), "r"(v));
}
__device__ __forceinline__ float retanh(float x) {
    float xm = fmaxf(x, 0.0f);
    float e;
    asm("ex2.approx.f32 %0, %1;" : "=f"(e) : "f"(xm * -2.885390082f));
    return __fdividef(1.0f - e, 1.0f + e);
}

// ======================= SGEMM (proven R7 double-buffered) ====================
#define BM 128
#define BN 128
#define BK 16

__global__ __launch_bounds__(256, 2) void sgemm_kernel(
    const float* __restrict__ A, const float* __restrict__ B,
    const float* __restrict__ bias1, const float* __restrict__ bias2,
    float* __restrict__ C, int M, int Nc, int K, int D1, int D2, int act)
{
    __shared__ float As[2][BK][BM + 8];
    __shared__ float Bs[2][BK][BN + 8];

    const int tid = threadIdx.x;
    const int m0 = blockIdx.y * BM;
    const int j0 = blockIdx.x * BN;
    const int tm = tid >> 4;
    const int tn = tid & 15;
    const int lr = tid >> 2;
    const int lk = (tid & 3) * 4;

    const float* ap0 = A + (size_t)(m0 + lr) * K + lk;
    const float* ap1 = A + (size_t)(m0 + lr + 64) * K + lk;
    const float* bp0 = B + (size_t)(j0 + lr) * K + lk;
    const float* bp1 = B + (size_t)(j0 + lr + 64) * K + lk;

    unsigned long long acc[8][4];
#pragma unroll
    for (int i = 0; i < 8; i++)
#pragma unroll
        for (int j = 0; j < 4; j++) acc[i][j] = 0ull;

    {
        float4 pa0 = *(const float4*)ap0;
        float4 pa1 = *(const float4*)ap1;
        float4 pb0 = *(const float4*)bp0;
        float4 pb1 = *(const float4*)bp1;
        As[0][lk + 0][lr] = pa0.x; As[0][lk + 1][lr] = pa0.y;
        As[0][lk + 2][lr] = pa0.z; As[0][lk + 3][lr] = pa0.w;
        As[0][lk + 0][lr + 64] = pa1.x; As[0][lk + 1][lr + 64] = pa1.y;
        As[0][lk + 2][lr + 64] = pa1.z; As[0][lk + 3][lr + 64] = pa1.w;
        Bs[0][lk + 0][lr] = pb0.x; Bs[0][lk + 1][lr] = pb0.y;
        Bs[0][lk + 2][lr] = pb0.z; Bs[0][lk + 3][lr] = pb0.w;
        Bs[0][lk + 0][lr + 64] = pb1.x; Bs[0][lk + 1][lr + 64] = pb1.y;
        Bs[0][lk + 2][lr + 64] = pb1.z; Bs[0][lk + 3][lr + 64] = pb1.w;
    }
    __syncthreads();

    int cur = 0;
    for (int kt = 0; kt < K; kt += BK) {
        float4 pa0, pa1, pb0, pb1;
        const bool more = (kt + BK < K);
        if (more) {
            pa0 = *(const float4*)(ap0 + kt + BK);
            pa1 = *(const float4*)(ap1 + kt + BK);
            pb0 = *(const float4*)(bp0 + kt + BK);
            pb1 = *(const float4*)(bp1 + kt + BK);
        }
#pragma unroll
        for (int kk = 0; kk < BK; kk++) {
            float a[8];
            *(float4*)&a[0] = *(const float4*)&As[cur][kk][tm * 8];
            *(float4*)&a[4] = *(const float4*)&As[cur][kk][tm * 8 + 4];
            ulonglong2 b01 = *(const ulonglong2*)&Bs[cur][kk][tn * 8];
            ulonglong2 b23 = *(const ulonglong2*)&Bs[cur][kk][tn * 8 + 4];
#pragma unroll
            for (int i = 0; i < 8; i++) {
                unsigned long long ad = dup2(a[i]);
                fma2(acc[i][0], ad, b01.x);
                fma2(acc[i][1], ad, b01.y);
                fma2(acc[i][2], ad, b23.x);
                fma2(acc[i][3], ad, b23.y);
            }
        }
        if (more) {
            const int nxt = cur ^ 1;
            As[nxt][lk + 0][lr] = pa0.x; As[nxt][lk + 1][lr] = pa0.y;
            As[nxt][lk + 2][lr] = pa0.z; As[nxt][lk + 3][lr] = pa0.w;
            As[nxt][lk + 0][lr + 64] = pa1.x; As[nxt][lk + 1][lr + 64] = pa1.y;
            As[nxt][lk + 2][lr + 64] = pa1.z; As[nxt][lk + 3][lr + 64] = pa1.w;
            Bs[nxt][lk + 0][lr] = pb0.x; Bs[nxt][lk + 1][lr] = pb0.y;
            Bs[nxt][lk + 2][lr] = pb0.z; Bs[nxt][lk + 3][lr] = pb0.w;
            Bs[nxt][lk + 0][lr + 64] = pb1.x; Bs[nxt][lk + 1][lr + 64] = pb1.y;
            Bs[nxt][lk + 2][lr + 64] = pb1.z; Bs[nxt][lk + 3][lr + 64] = pb1.w;
            __syncthreads();
            cur = nxt;
        }
    }

    float bcol[8];
#pragma unroll
    for (int j = 0; j < 8; j++) {
        const int cn = j0 + tn * 8 + j;
        float b = bias1[cn];
        if (bias2) b += bias2[cn];
        bcol[j] = b;
    }
#pragma unroll
    for (int i = 0; i < 8; i++) {
        const int rm = m0 + tm * 8 + i;
        const int orow = (rm % D1) * D2 + (rm / D1);
        float out[8];
#pragma unroll
        for (int j = 0; j < 4; j++) {
            out[2 * j + 0] = lo32(acc[i][j]) + bcol[2 * j + 0];
            out[2 * j + 1] = hi32(acc[i][j]) + bcol[2 * j + 1];
        }
        if (act) {
#pragma unroll
            for (int j = 0; j < 8; j++) out[j] = retanh(out[j]);
        }
        float* cp = C + (size_t)orow * Nc + j0 + tn * 8;
        *(float4*)cp       = *(float4*)&out[0];
        *(float4*)(cp + 4) = *(float4*)&out[4];
    }
}

// ======================= helpers ==============================================
__global__ __launch_bounds__(512) void transpose_h0(
    const float* __restrict__ h0, float* __restrict__ hx)
{
    const int idx = blockIdx.x * 512 + threadIdx.x;
    hx[idx] = h0[(size_t)(idx & 63) * HH + (idx >> 6)];
}

__global__ __launch_bounds__(1024) void reset_flags_kernel() {
    g_gflag[threadIdx.x] = 0u;
}

// ======================= persistent recurrence ================================
// 128 CTAs = 2 halves x 64 column-slices. 16 warps own 64-wide k-chunks.
// Per-warp column publish (coalesced) + per-warp release flags (target 64t).
#define RGRID 128
#define RTHR  512
#define RSMEM ((16384 + 9216 + 544) * 4)   // Whs + redU + sv

__global__ __launch_bounds__(RTHR) void recur_kernel(
    float* __restrict__ buf, const float* __restrict__ Wh,
    float* __restrict__ hx0, float* __restrict__ hx1)
{
    extern __shared__ float smem[];
    float* Whs = smem;                                                // [1024][16]
    unsigned long long* redU = (unsigned long long*)(smem + 16384);   // [16][32][9]
    float* sv = smem + 16384 + 9216;                                  // [16][33]

    const int tid  = threadIdx.x;
    const int bidb = blockIdx.x >> 6;
    const int bidh = blockIdx.x & 63;
    const int nb0  = bidb * 32;
    const int c0   = bidh * 16;

    {   // Wh slice transposed into SMEM: Whs[k][cl] = Wh[c0+cl][k]
        const int cl = tid & 15;
        const int kb = (tid >> 4) * 32;
        const float* wrow = Wh + (size_t)(c0 + cl) * HH + kb;
#pragma unroll
        for (int kk = 0; kk < 32; kk++) Whs[(kb + kk) * 16 + cl] = wrow[kk];
    }
    __syncthreads();

    const int wid  = tid >> 5;
    const int lane = tid & 31;
    const int k0   = wid * 64;
    const int cR   = lane & 15;
    const int nR   = 2 * wid + (lane >> 4);
    const float* redF = (const float*)redU;

    const unsigned* wf = &g_gflag[(bidb * 16 + wid) * 32];
    unsigned* pf = &g_gflag[(bidb * 16 + (bidh >> 2)) * 32];

    for (int t = 0; t < TT; t++) {
        const float* hp = ((t & 1) ? hx1 : hx0) + (size_t)k0 * NB + nb0 + lane;
        float*       hn = ((t & 1) ? hx0 : hx1);
        float* outp = buf + (size_t)t * NHh + (size_t)(nb0 + nR) * HH + (c0 + cR);
        const float x_pre = __ldcg(outp);

        {   // wait: 4 source slices x 16 warps published step t-1
            const unsigned tgt = 64u * (unsigned)t;
            int spins = 0;
            while (ld_acq(wf) < tgt) { if (++spins > 64) __nanosleep(64); }
        }

        unsigned long long acc[8];
#pragma unroll
        for (int j = 0; j < 8; j++) acc[j] = 0ull;

        float hbuf[3][8];
#pragma unroll
        for (int j = 0; j < 8; j++) hbuf[0][j] = __ldcg(hp + (size_t)j * NB);
#pragma unroll
        for (int j = 0; j < 8; j++) hbuf[1][j] = __ldcg(hp + (size_t)(8 + j) * NB);

#pragma unroll
        for (int g = 0; g < 8; g++) {
            if (g + 2 < 8) {
#pragma unroll
                for (int j = 0; j < 8; j++)
                    hbuf[(g + 2) % 3][j] = __ldcg(hp + (size_t)((g + 2) * 8 + j) * NB);
            }
#pragma unroll
            for (int j = 0; j < 8; j++) {
                const unsigned long long ad = dup2(hbuf[g % 3][j]);
                const float* wk = &Whs[(k0 + g * 8 + j) * 16];
                ulonglong2 w0 = *(const ulonglong2*)(wk + 0);
                ulonglong2 w1 = *(const ulonglong2*)(wk + 4);
                ulonglong2 w2 = *(const ulonglong2*)(wk + 8);
                ulonglong2 w3 = *(const ulonglong2*)(wk + 12);
                fma2(acc[0], ad, w0.x); fma2(acc[1], ad, w0.y);
                fma2(acc[2], ad, w1.x); fma2(acc[3], ad, w1.y);
                fma2(acc[4], ad, w2.x); fma2(acc[5], ad, w2.y);
                fma2(acc[6], ad, w3.x); fma2(acc[7], ad, w3.y);
            }
        }

        {   // partials -> redU[wid][lane][0..7]
            unsigned long long* rp = &redU[(size_t)(wid * 32 + lane) * 9];
#pragma unroll
            for (int j = 0; j < 8; j++) rp[j] = acc[j];
        }
        __syncthreads();   // A

        // reduce 16 k-chunks for (n=nR, c=cR); store buf + stage for publish
        float s = 0.0f;
#pragma unroll
        for (int w = 0; w < 16; w++) s += redF[(w * 32 + nR) * 18 + cR];
        const float v = retanh(s + x_pre);
        *outp = v;                 // [T,N,H] for downstream GEMM (2 lines/warp)
        sv[cR * 33 + nR] = v;      // conflict-free SMEM stage
        __syncthreads();   // B

        // warp wid publishes column c0+wid: one coalesced 128B line
        hn[(size_t)(c0 + wid) * NB + nb0 + lane] = sv[wid * 33 + lane];
        __syncwarp();
        if (lane == 0) red_rel(pf, 1u);   // per-warp arrival (64 per step)
    }
}

// ======================= launcher ==============================================
static void launch_gemm(const float* A, const float* B, const float* b1,
                        const float* b2, float* C, int M, int Nc, int K,
                        int D1, int D2, int act)
{
    dim3 grid(Nc / BN, M / BM);
    sgemm_kernel<<<grid, 256>>>(A, B, b1, b2, C, M, Nc, K, D1, D2, act);
}

extern "C" void kernel_launch(void* const* d_in, const int* in_sizes, int n_in,
                              void* d_out, int out_size)
{
    const float* data = (const float*)d_in[0];
    const float* h0_v = (const float*)d_in[1];
    const float* h0_m = (const float*)d_in[2];
    const float* Wi   = (const float*)d_in[3];
    const float* bi   = (const float*)d_in[4];
    const float* Wh   = (const float*)d_in[5];
    const float* bh   = (const float*)d_in[6];
    const float* Wo   = (const float*)d_in[7];
    const float* bo   = (const float*)d_in[8];
    const float* Wt   = (const float*)d_in[9];
    const float* bt   = (const float*)d_in[10];
    const float* Wi2  = (const float*)d_in[11];
    const float* bi2  = (const float*)d_in[12];
    const float* Wh2  = (const float*)d_in[13];
    const float* bh2  = (const float*)d_in[14];
    const float* Wo2  = (const float*)d_in[15];
    const float* bo2  = (const float*)d_in[16];
    float* out = (float*)d_out;

    float *bufA, *bufB, *bufO, *bufO2, *hx0, *hx1;
    cudaGetSymbolAddress((void**)&bufA,  g_bufA);
    cudaGetSymbolAddress((void**)&bufB,  g_bufB);
    cudaGetSymbolAddress((void**)&bufO,  g_bufO);
    cudaGetSymbolAddress((void**)&bufO2, g_bufO2);
    cudaGetSymbolAddress((void**)&hx0,   g_hx0);
    cudaGetSymbolAddress((void**)&hx1,   g_hx1);

    cudaFuncSetAttribute(recur_kernel,
                         cudaFuncAttributeMaxDynamicSharedMemorySize, RSMEM);

    // 1) inp_v = data @ Wi^T + (bi + bh) -> [T,N,H]
    launch_gemm(data, Wi, bi, bh, bufA, NT, HH, II, TT, NB, 0);
    // 2) visual recurrence
    transpose_h0<<<128, 512>>>(h0_v, hx0);
    reset_flags_kernel<<<1, 1024>>>();
    recur_kernel<<<RGRID, RTHR, RSMEM>>>(bufA, Wh, hx0, hx1);
    // 3) out_v = hs_v @ Wo^T + bo -> [N,T,O]
    launch_gemm(bufA, Wo, bo, nullptr, bufO, NT, OO, HH, NB, TT, 0);
    // 4) out_t = retanh(out_v @ Wt^T + bt)
    launch_gemm(bufO, Wt, bt, nullptr, bufO2, NT, OO, OO, NT, 1, 1);
    // 5) inp_m = out_t @ Wi2^T + (bi2 + bh2) -> [T,N,H]
    launch_gemm(bufO2, Wi2, bi2, bh2, bufB, NT, HH, OO, TT, NB, 0);
    // 6) motor recurrence
    transpose_h0<<<128, 512>>>(h0_m, hx0);
    reset_flags_kernel<<<1, 1024>>>();
    recur_kernel<<<RGRID, RTHR, RSMEM>>>(bufB, Wh2, hx0, hx1);
    // 7) out_m = hs_m @ Wo2^T + bo2 -> [N,T,O]
    launch_gemm(bufB, Wo2, bo2, nullptr, out, NT, OO, HH, NB, TT, 0);
}

// round 12
// speedup vs baseline: 1.6618x; 1.1766x over previous
#include <cuda_runtime.h>
#include <cuda_bf16.h>
#include <cstdint>

#define NB 64
#define TT 512
#define II 512
#define HH 1024
#define OO 512
#define NT (NB*TT)
#define NHh (NB*HH)

// ---------------- scratch ------------------------------------------------------
__device__ float g_bufA[TT*NB*HH];
__device__ float g_bufB[TT*NB*HH];
__device__ float g_bufO[NT*OO];
__device__ float g_bufO2[NT*OO];
__device__ float g_hx0[HH*NB];
__device__ float g_hx1[HH*NB];
__device__ unsigned g_gflag[32*32];
// bf16 split buffers
__device__ __nv_bfloat16 g_dHi[NT*II],  g_dLo[NT*II];
__device__ __nv_bfloat16 g_aHi[NT*HH],  g_aLo[NT*HH];
__device__ __nv_bfloat16 g_oHi[NT*OO],  g_oLo[NT*OO];
__device__ __nv_bfloat16 g_o2Hi[NT*OO], g_o2Lo[NT*OO];
__device__ __nv_bfloat16 g_WiH[HH*II],  g_WiL[HH*II];
__device__ __nv_bfloat16 g_WoH[OO*HH],  g_WoL[OO*HH];
__device__ __nv_bfloat16 g_WtH[OO*OO],  g_WtL[OO*OO];
__device__ __nv_bfloat16 g_Wi2H[HH*OO], g_Wi2L[HH*OO];
__device__ __nv_bfloat16 g_Wo2H[OO*HH], g_Wo2L[OO*HH];

// ---------------- helpers ------------------------------------------------------
__device__ __forceinline__ unsigned long long dup2(float a) {
    unsigned long long r; asm("mov.b64 %0, {%1, %1};" : "=l"(r) : "f"(a)); return r;
}
__device__ __forceinline__ void fma2(unsigned long long& c, unsigned long long a,
                                     unsigned long long b) {
    asm("fma.rn.f32x2 %0, %1, %2, %0;" : "+l"(c) : "l"(a), "l"(b));
}
__device__ __forceinline__ unsigned ld_acq(const unsigned* p) {
    unsigned v;
    asm volatile("ld.acquire.gpu.global.u32 %0, [%1];" : "=r"(v) : "l"(p));
    return v;
}
__device__ __forceinline__ void red_rel(unsigned* p, unsigned v) {
    asm volatile("red.add.release.gpu.global.u32 [%0], %1;" :: "l"(p), "r"(v));
}
__device__ __forceinline__ float retanh(float x) {
    float xm = fmaxf(x, 0.0f);
    float e;
    asm("ex2.approx.f32 %0, %1;" : "=f"(e) : "f"(xm * -2.885390082f));
    return __fdividef(1.0f - e, 1.0f + e);
}
__device__ __forceinline__ uint32_t smem_u32(const void* p) {
    uint32_t a;
    asm("{ .reg .u64 t; cvta.to.shared.u64 t, %1; cvt.u32.u64 %0, t; }"
        : "=r"(a) : "l"(p));
    return a;
}
__device__ __forceinline__ void ldmx4(uint32_t* r, uint32_t addr) {
    asm volatile("ldmatrix.sync.aligned.m8n8.x4.shared.b16 {%0,%1,%2,%3}, [%4];"
                 : "=r"(r[0]), "=r"(r[1]), "=r"(r[2]), "=r"(r[3]) : "r"(addr));
}
__device__ __forceinline__ void mma16816(float* c, const uint32_t* a,
                                         uint32_t b0, uint32_t b1) {
    asm volatile(
        "mma.sync.aligned.m16n8k16.row.col.f32.bf16.bf16.f32 "
        "{%0,%1,%2,%3}, {%4,%5,%6,%7}, {%8,%9}, {%0,%1,%2,%3};"
        : "+f"(c[0]), "+f"(c[1]), "+f"(c[2]), "+f"(c[3])
        : "r"(a[0]), "r"(a[1]), "r"(a[2]), "r"(a[3]), "r"(b0), "r"(b1));
}

// ======================= HMMA GEMM (split-bf16, 3 passes) =====================
// C[remap(m)][j0..j0+127] = (Ahi+Alo)[m,:K] @ (Bhi+Blo)[j,:K]^T + bias
// Tile 128x128x32, 8 warps (4m x 2n), warp tile 32x64. Double-buffered SMEM.
__global__ __launch_bounds__(256, 2) void hgemm(
    const __nv_bfloat16* __restrict__ Ahi, const __nv_bfloat16* __restrict__ Alo,
    const __nv_bfloat16* __restrict__ Bhi, const __nv_bfloat16* __restrict__ Blo,
    const float* __restrict__ b1, const float* __restrict__ b2,
    float* __restrict__ C, int K, int Nc, int D1, int D2, int act)
{
    __shared__ __align__(16) __nv_bfloat16 smA[2][128 * 40];
    __shared__ __align__(16) __nv_bfloat16 smB[2][128 * 40];

    const int tid = threadIdx.x, lane = tid & 31, wid = tid >> 5;
    const int m0 = blockIdx.y * 128, j0 = blockIdx.x * 128;
    const int wm = wid & 3, wn = wid >> 2;
    const int lrow = tid >> 1, lhalf = tid & 1;
    const int KC = K / 32, NCH = 3 * KC;

    float acc[2][8][4];
#pragma unroll
    for (int i = 0; i < 2; i++)
#pragma unroll
        for (int j = 0; j < 8; j++)
#pragma unroll
            for (int q = 0; q < 4; q++) acc[i][j][q] = 0.0f;

    // chunk c -> pass p, k-offset kt, source pointers
    // p0: Ahi*Bhi  p1: Ahi*Blo  p2: Alo*Bhi
    const __nv_bfloat16* pA;
    const __nv_bfloat16* pB;
    int kt;
    {
        pA = Ahi; pB = Bhi; kt = 0;
    }
    uint4 ra0, ra1, rb0, rb1;
    {
        const uint4* ga = (const uint4*)(pA + (size_t)(m0 + lrow) * K + kt + lhalf * 16);
        ra0 = ga[0]; ra1 = ga[1];
        const uint4* gb = (const uint4*)(pB + (size_t)(j0 + lrow) * K + kt + lhalf * 16);
        rb0 = gb[0]; rb1 = gb[1];
    }
    {
        uint4* da = (uint4*)(&smA[0][lrow * 40 + lhalf * 16]);
        da[0] = ra0; da[1] = ra1;
        uint4* db = (uint4*)(&smB[0][lrow * 40 + lhalf * 16]);
        db[0] = rb0; db[1] = rb1;
    }
    __syncthreads();

    int cur = 0;
    for (int c = 0; c < NCH; c++) {
        const bool more = (c + 1 < NCH);
        if (more) {
            const int cn = c + 1;
            const int p = cn / KC;
            kt = (cn - p * KC) * 32;
            pA = (p == 2) ? Alo : Ahi;
            pB = (p == 1) ? Blo : Bhi;
            const uint4* ga = (const uint4*)(pA + (size_t)(m0 + lrow) * K + kt + lhalf * 16);
            ra0 = ga[0]; ra1 = ga[1];
            const uint4* gb = (const uint4*)(pB + (size_t)(j0 + lrow) * K + kt + lhalf * 16);
            rb0 = gb[0]; rb1 = gb[1];
        }

        const uint32_t baseA = smem_u32(&smA[cur][0]);
        const uint32_t baseB = smem_u32(&smB[cur][0]);
#pragma unroll
        for (int kk = 0; kk < 2; kk++) {
            uint32_t aF[2][4], bF[4][4];
#pragma unroll
            for (int mt = 0; mt < 2; mt++)
                ldmx4(aF[mt], baseA +
                      ((wm * 32 + mt * 16 + (lane & 15)) * 40 + kk * 16 + (lane >> 4) * 8) * 2);
#pragma unroll
            for (int np = 0; np < 4; np++)
                ldmx4(bF[np], baseB +
                      ((wn * 64 + np * 16 + (lane & 15)) * 40 + kk * 16 + (lane >> 4) * 8) * 2);
#pragma unroll
            for (int mt = 0; mt < 2; mt++)
#pragma unroll
                for (int np = 0; np < 4; np++) {
                    mma16816(acc[mt][2 * np + 0], aF[mt], bF[np][0], bF[np][2]);
                    mma16816(acc[mt][2 * np + 1], aF[mt], bF[np][1], bF[np][3]);
                }
        }

        if (more) {
            const int nxt = cur ^ 1;
            uint4* da = (uint4*)(&smA[nxt][lrow * 40 + lhalf * 16]);
            da[0] = ra0; da[1] = ra1;
            uint4* db = (uint4*)(&smB[nxt][lrow * 40 + lhalf * 16]);
            db[0] = rb0; db[1] = rb1;
            __syncthreads();
            cur = nxt;
        }
    }

    // epilogue: bias (+b2), optional retanh, row remap, float2 stores
#pragma unroll
    for (int mt = 0; mt < 2; mt++) {
        const int rbase = m0 + wm * 32 + mt * 16 + (lane >> 2);
#pragma unroll
        for (int half = 0; half < 2; half++) {
            const int rm = rbase + half * 8;
            const int orow = (rm % D1) * D2 + rm / D1;
            float* cp = C + (size_t)orow * Nc;
#pragma unroll
            for (int nt = 0; nt < 8; nt++) {
                const int cn = j0 + wn * 64 + nt * 8 + (lane & 3) * 2;
                float bb0 = b1[cn], bb1 = b1[cn + 1];
                if (b2) { bb0 += b2[cn]; bb1 += b2[cn + 1]; }
                float x = acc[mt][nt][2 * half + 0] + bb0;
                float y = acc[mt][nt][2 * half + 1] + bb1;
                if (act) { x = retanh(x); y = retanh(y); }
                float2 v; v.x = x; v.y = y;
                *(float2*)(cp + cn) = v;
            }
        }
    }
}

// ======================= fp32 -> bf16 hi/lo split ==============================
__global__ __launch_bounds__(256) void cvt_split(
    const float* __restrict__ x, __nv_bfloat16* __restrict__ hi,
    __nv_bfloat16* __restrict__ lo, int n4)
{
    const int i = blockIdx.x * 256 + threadIdx.x;
    if (i >= n4) return;
    const float4 v = ((const float4*)x)[i];
    __nv_bfloat16 h0 = __float2bfloat16(v.x), h1 = __float2bfloat16(v.y);
    __nv_bfloat16 h2 = __float2bfloat16(v.z), h3 = __float2bfloat16(v.w);
    __nv_bfloat16 l0 = __float2bfloat16(v.x - __bfloat162float(h0));
    __nv_bfloat16 l1 = __float2bfloat16(v.y - __bfloat162float(h1));
    __nv_bfloat16 l2 = __float2bfloat16(v.z - __bfloat162float(h2));
    __nv_bfloat16 l3 = __float2bfloat16(v.w - __bfloat162float(h3));
    ((__nv_bfloat162*)hi)[2 * i]     = __nv_bfloat162(h0, h1);
    ((__nv_bfloat162*)hi)[2 * i + 1] = __nv_bfloat162(h2, h3);
    ((__nv_bfloat162*)lo)[2 * i]     = __nv_bfloat162(l0, l1);
    ((__nv_bfloat162*)lo)[2 * i + 1] = __nv_bfloat162(l2, l3);
}

// ======================= helpers ==============================================
__global__ __launch_bounds__(512) void transpose_h0(
    const float* __restrict__ h0, float* __restrict__ hx)
{
    const int idx = blockIdx.x * 512 + threadIdx.x;
    hx[idx] = h0[(size_t)(idx & 63) * HH + (idx >> 6)];
}
__global__ __launch_bounds__(1024) void reset_flags_kernel() {
    g_gflag[threadIdx.x] = 0u;
}

// ======================= persistent recurrence (9758-benched) =================
#define RGRID 128
#define RTHR  512
#define RSMEM ((16384 + 9216) * 4)

__global__ __launch_bounds__(RTHR) void recur_kernel(
    float* __restrict__ buf, const float* __restrict__ Wh,
    float* __restrict__ hx0, float* __restrict__ hx1)
{
    extern __shared__ float smem[];
    float* Whs = smem;                                                // [1024][16]
    unsigned long long* redU = (unsigned long long*)(smem + 16384);   // [16][32][9]

    const int tid  = threadIdx.x;
    const int bidb = blockIdx.x >> 6;
    const int bidh = blockIdx.x & 63;
    const int nb0  = bidb * 32;
    const int c0   = bidh * 16;

    {
        const int cl = tid & 15;
        const int kb = (tid >> 4) * 32;
        const float* wrow = Wh + (size_t)(c0 + cl) * HH + kb;
#pragma unroll
        for (int kk = 0; kk < 32; kk++) Whs[(kb + kk) * 16 + cl] = wrow[kk];
    }
    __syncthreads();

    const int wid  = tid >> 5;
    const int lane = tid & 31;
    const int k0   = wid * 64;
    const int cR   = lane & 15;
    const int nR   = 2 * wid + (lane >> 4);
    const float* redF = (const float*)redU;

    const unsigned* wf = &g_gflag[(bidb * 16 + wid) * 32];
    unsigned* pf = &g_gflag[(bidb * 16 + (bidh >> 2)) * 32];

    for (int t = 0; t < TT; t++) {
        const float* hp = ((t & 1) ? hx1 : hx0) + (size_t)k0 * NB + nb0 + lane;
        float*       hn = ((t & 1) ? hx0 : hx1);
        float* outp = buf + (size_t)t * NHh + (size_t)(nb0 + nR) * HH + (c0 + cR);
        const float x_pre = __ldcg(outp);
        {
            const unsigned tgt = 4u * (unsigned)t;
            while (ld_acq(wf) < tgt) __nanosleep(20);
        }
        unsigned long long acc[8];
#pragma unroll
        for (int j = 0; j < 8; j++) acc[j] = 0ull;
        float hbuf[3][8];
#pragma unroll
        for (int j = 0; j < 8; j++) hbuf[0][j] = __ldcg(hp + (size_t)j * NB);
#pragma unroll
        for (int j = 0; j < 8; j++) hbuf[1][j] = __ldcg(hp + (size_t)(8 + j) * NB);
#pragma unroll
        for (int g = 0; g < 8; g++) {
            if (g + 2 < 8) {
#pragma unroll
                for (int j = 0; j < 8; j++)
                    hbuf[(g + 2) % 3][j] = __ldcg(hp + (size_t)((g + 2) * 8 + j) * NB);
            }
#pragma unroll
            for (int j = 0; j < 8; j++) {
                const unsigned long long ad = dup2(hbuf[g % 3][j]);
                const float* wk = &Whs[(k0 + g * 8 + j) * 16];
                ulonglong2 w0 = *(const ulonglong2*)(wk + 0);
                ulonglong2 w1 = *(const ulonglong2*)(wk + 4);
                ulonglong2 w2 = *(const ulonglong2*)(wk + 8);
                ulonglong2 w3 = *(const ulonglong2*)(wk + 12);
                fma2(acc[0], ad, w0.x); fma2(acc[1], ad, w0.y);
                fma2(acc[2], ad, w1.x); fma2(acc[3], ad, w1.y);
                fma2(acc[4], ad, w2.x); fma2(acc[5], ad, w2.y);
                fma2(acc[6], ad, w3.x); fma2(acc[7], ad, w3.y);
            }
        }
        {
            unsigned long long* rp = &redU[(size_t)(wid * 32 + lane) * 9];
#pragma unroll
            for (int j = 0; j < 8; j++) rp[j] = acc[j];
        }
        __syncthreads();
        float s = 0.0f;
#pragma unroll
        for (int w = 0; w < 16; w++) s += redF[(w * 32 + nR) * 18 + cR];
        const float v = retanh(s + x_pre);
        *outp = v;
        hn[(size_t)(c0 + cR) * NB + nb0 + nR] = v;
        __syncthreads();
        if (tid == 0) red_rel(pf, 1u);
    }
}

// ======================= launcher ==============================================
static void cvt(const float* x, __nv_bfloat16* hi, __nv_bfloat16* lo, int n) {
    const int n4 = n / 4;
    cvt_split<<<(n4 + 255) / 256, 256>>>(x, hi, lo, n4);
}

extern "C" void kernel_launch(void* const* d_in, const int* in_sizes, int n_in,
                              void* d_out, int out_size)
{
    const float* data = (const float*)d_in[0];
    const float* h0_v = (const float*)d_in[1];
    const float* h0_m = (const float*)d_in[2];
    const float* Wi   = (const float*)d_in[3];
    const float* bi   = (const float*)d_in[4];
    const float* Wh   = (const float*)d_in[5];
    const float* bh   = (const float*)d_in[6];
    const float* Wo   = (const float*)d_in[7];
    const float* bo   = (const float*)d_in[8];
    const float* Wt   = (const float*)d_in[9];
    const float* bt   = (const float*)d_in[10];
    const float* Wi2  = (const float*)d_in[11];
    const float* bi2  = (const float*)d_in[12];
    const float* Wh2  = (const float*)d_in[13];
    const float* bh2  = (const float*)d_in[14];
    const float* Wo2  = (const float*)d_in[15];
    const float* bo2  = (const float*)d_in[16];
    float* out = (float*)d_out;

    float *bufA, *bufB, *bufO, *bufO2, *hx0, *hx1;
    cudaGetSymbolAddress((void**)&bufA,  g_bufA);
    cudaGetSymbolAddress((void**)&bufB,  g_bufB);
    cudaGetSymbolAddress((void**)&bufO,  g_bufO);
    cudaGetSymbolAddress((void**)&bufO2, g_bufO2);
    cudaGetSymbolAddress((void**)&hx0,   g_hx0);
    cudaGetSymbolAddress((void**)&hx1,   g_hx1);
    __nv_bfloat16 *dH,*dL,*aH,*aL,*oH,*oL,*o2H,*o2L;
    __nv_bfloat16 *WiH,*WiL,*WoH,*WoL,*WtH,*WtL,*Wi2H,*Wi2L,*Wo2H,*Wo2L;
    cudaGetSymbolAddress((void**)&dH, g_dHi);   cudaGetSymbolAddress((void**)&dL, g_dLo);
    cudaGetSymbolAddress((void**)&aH, g_aHi);   cudaGetSymbolAddress((void**)&aL, g_aLo);
    cudaGetSymbolAddress((void**)&oH, g_oHi);   cudaGetSymbolAddress((void**)&oL, g_oLo);
    cudaGetSymbolAddress((void**)&o2H, g_o2Hi); cudaGetSymbolAddress((void**)&o2L, g_o2Lo);
    cudaGetSymbolAddress((void**)&WiH, g_WiH);  cudaGetSymbolAddress((void**)&WiL, g_WiL);
    cudaGetSymbolAddress((void**)&WoH, g_WoH);  cudaGetSymbolAddress((void**)&WoL, g_WoL);
    cudaGetSymbolAddress((void**)&WtH, g_WtH);  cudaGetSymbolAddress((void**)&WtL, g_WtL);
    cudaGetSymbolAddress((void**)&Wi2H, g_Wi2H); cudaGetSymbolAddress((void**)&Wi2L, g_Wi2L);
    cudaGetSymbolAddress((void**)&Wo2H, g_Wo2H); cudaGetSymbolAddress((void**)&Wo2L, g_Wo2L);

    cudaFuncSetAttribute(recur_kernel,
                         cudaFuncAttributeMaxDynamicSharedMemorySize, RSMEM);

    // weight + data converts
    cvt(Wi,  WiH,  WiL,  HH * II);
    cvt(Wo,  WoH,  WoL,  OO * HH);
    cvt(Wt,  WtH,  WtL,  OO * OO);
    cvt(Wi2, Wi2H, Wi2L, HH * OO);
    cvt(Wo2, Wo2H, Wo2L, OO * HH);
    cvt(data, dH, dL, NT * II);

    // G1: inp_v = data @ Wi^T + (bi+bh) -> [T,N,H]
    hgemm<<<dim3(HH / 128, NT / 128), 256>>>(
        dH, dL, WiH, WiL, bi, bh, bufA, II, HH, TT, NB, 0);
    // visual recurrence
    transpose_h0<<<128, 512>>>(h0_v, hx0);
    reset_flags_kernel<<<1, 1024>>>();
    recur_kernel<<<RGRID, RTHR, RSMEM>>>(bufA, Wh, hx0, hx1);
    // G3: out_v = hs_v @ Wo^T + bo -> [N,T,O]
    cvt(bufA, aH, aL, NT * HH);
    hgemm<<<dim3(OO / 128, NT / 128), 256>>>(
        aH, aL, WoH, WoL, bo, nullptr, bufO, HH, OO, NB, TT, 0);
    // G4: out_t = retanh(out_v @ Wt^T + bt)
    cvt(bufO, oH, oL, NT * OO);
    hgemm<<<dim3(OO / 128, NT / 128), 256>>>(
        oH, oL, WtH, WtL, bt, nullptr, bufO2, OO, OO, NT, 1, 1);
    // G5: inp_m = out_t @ Wi2^T + (bi2+bh2) -> [T,N,H]
    cvt(bufO2, o2H, o2L, NT * OO);
    hgemm<<<dim3(HH / 128, NT / 128), 256>>>(
        o2H, o2L, Wi2H, Wi2L, bi2, bh2, bufB, OO, HH, TT, NB, 0);
    // motor recurrence
    transpose_h0<<<128, 512>>>(h0_m, hx0);
    reset_flags_kernel<<<1, 1024>>>();
    recur_kernel<<<RGRID, RTHR, RSMEM>>>(bufB, Wh2, hx0, hx1);
    // G7: out_m = hs_m @ Wo2^T + bo2 -> [N,T,O]
    cvt(bufB, aH, aL, NT * HH);
    hgemm<<<dim3(OO / 128, NT / 128), 256>>>(
        aH, aL, Wo2H, Wo2L, bo2, nullptr, out, HH, OO, NB, TT, 0);
}

// round 13
// speedup vs baseline: 1.6723x; 1.0063x over previous
#include <cuda_runtime.h>
#include <cuda_bf16.h>
#include <cstdint>

#define NB 64
#define TT 512
#define II 512
#define HH 1024
#define OO 512
#define NT (NB*TT)
#define NHh (NB*HH)

// ---------------- scratch ------------------------------------------------------
__device__ float g_bufA[TT*NB*HH];
__device__ float g_bufB[TT*NB*HH];
__device__ float g_hx0[HH*NB];
__device__ float g_hx1[HH*NB];
__device__ unsigned g_gflag[32*32];
// bf16 split buffers
__device__ __nv_bfloat16 g_dHi[NT*II],  g_dLo[NT*II];
__device__ __nv_bfloat16 g_aHi[NT*HH],  g_aLo[NT*HH];    // hs (written by recur)
__device__ __nv_bfloat16 g_oHi[NT*OO],  g_oLo[NT*OO];    // out_v (written by G3)
__device__ __nv_bfloat16 g_o2Hi[NT*OO], g_o2Lo[NT*OO];   // out_t (written by G4)
__device__ __nv_bfloat16 g_WiH[HH*II],  g_WiL[HH*II];
__device__ __nv_bfloat16 g_WoH[OO*HH],  g_WoL[OO*HH];
__device__ __nv_bfloat16 g_WtH[OO*OO],  g_WtL[OO*OO];
__device__ __nv_bfloat16 g_Wi2H[HH*OO], g_Wi2L[HH*OO];
__device__ __nv_bfloat16 g_Wo2H[OO*HH], g_Wo2L[OO*HH];

// ---------------- helpers ------------------------------------------------------
__device__ __forceinline__ unsigned long long dup2(float a) {
    unsigned long long r; asm("mov.b64 %0, {%1, %1};" : "=l"(r) : "f"(a)); return r;
}
__device__ __forceinline__ void fma2(unsigned long long& c, unsigned long long a,
                                     unsigned long long b) {
    asm("fma.rn.f32x2 %0, %1, %2, %0;" : "+l"(c) : "l"(a), "l"(b));
}
__device__ __forceinline__ unsigned ld_acq(const unsigned* p) {
    unsigned v;
    asm volatile("ld.acquire.gpu.global.u32 %0, [%1];" : "=r"(v) : "l"(p));
    return v;
}
__device__ __forceinline__ void red_rel(unsigned* p, unsigned v) {
    asm volatile("red.add.release.gpu.global.u32 [%0], %1;" :: "l"(p), "r"(v));
}
__device__ __forceinline__ float retanh(float x) {
    float xm = fmaxf(x, 0.0f);
    float e;
    asm("ex2.approx.f32 %0, %1;" : "=f"(e) : "f"(xm * -2.885390082f));
    return __fdividef(1.0f - e, 1.0f + e);
}
__device__ __forceinline__ uint32_t smem_u32(const void* p) {
    uint32_t a;
    asm("{ .reg .u64 t; cvta.to.shared.u64 t, %1; cvt.u32.u64 %0, t; }"
        : "=r"(a) : "l"(p));
    return a;
}
__device__ __forceinline__ void ldmx4(uint32_t* r, uint32_t addr) {
    asm volatile("ldmatrix.sync.aligned.m8n8.x4.shared.b16 {%0,%1,%2,%3}, [%4];"
                 : "=r"(r[0]), "=r"(r[1]), "=r"(r[2]), "=r"(r[3]) : "r"(addr));
}
__device__ __forceinline__ void mma16816(float* c, const uint32_t* a,
                                         uint32_t b0, uint32_t b1) {
    asm volatile(
        "mma.sync.aligned.m16n8k16.row.col.f32.bf16.bf16.f32 "
        "{%0,%1,%2,%3}, {%4,%5,%6,%7}, {%8,%9}, {%0,%1,%2,%3};"
        : "+f"(c[0]), "+f"(c[1]), "+f"(c[2]), "+f"(c[3])
        : "r"(a[0]), "r"(a[1]), "r"(a[2]), "r"(a[3]), "r"(b0), "r"(b1));
}
__device__ __forceinline__ void cpa16(uint32_t dst, const void* src) {
    asm volatile("cp.async.cg.shared.global [%0], [%1], 16;"
                 :: "r"(dst), "l"(src) : "memory");
}
#define CPA_COMMIT asm volatile("cp.async.commit_group;" ::: "memory")
#define CPA_WAIT1  asm volatile("cp.async.wait_group 1;" ::: "memory")
#define CPA_WAIT0  asm volatile("cp.async.wait_group 0;" ::: "memory")

// ======================= HMMA GEMM (split-bf16, 3 passes, cp.async) ===========
// C = (Ahi+Alo) @ (Bhi+Blo)^T + bias; omode 0: fp32 C; 1: bf16 hi/lo split out.
__global__ __launch_bounds__(256, 2) void hgemm(
    const __nv_bfloat16* __restrict__ Ahi, const __nv_bfloat16* __restrict__ Alo,
    const __nv_bfloat16* __restrict__ Bhi, const __nv_bfloat16* __restrict__ Blo,
    const float* __restrict__ b1, const float* __restrict__ b2,
    float* __restrict__ C, __nv_bfloat16* __restrict__ hiO,
    __nv_bfloat16* __restrict__ loO,
    int K, int Nc, int D1, int D2, int act, int omode)
{
    __shared__ __align__(16) __nv_bfloat16 smA[2][128 * 40];
    __shared__ __align__(16) __nv_bfloat16 smB[2][128 * 40];

    const int tid = threadIdx.x, lane = tid & 31, wid = tid >> 5;
    const int m0 = blockIdx.y * 128, j0 = blockIdx.x * 128;
    const int wm = wid & 3, wn = wid >> 2;
    const int lrow = tid >> 1, lhalf = tid & 1;
    const int KC = K / 32, NCH = 3 * KC;

    float acc[2][8][4];
#pragma unroll
    for (int i = 0; i < 2; i++)
#pragma unroll
        for (int j = 0; j < 8; j++)
#pragma unroll
            for (int q = 0; q < 4; q++) acc[i][j][q] = 0.0f;

    // async copy of chunk c into buffer b (p0:Ahi*Bhi p1:Ahi*Blo p2:Alo*Bhi)
    auto copy_chunk = [&](int c, int b) {
        const int p = c / KC;
        const int kt = (c - p * KC) * 32;
        const __nv_bfloat16* pA = (p == 2) ? Alo : Ahi;
        const __nv_bfloat16* pB = (p == 1) ? Blo : Bhi;
        const uint32_t da = smem_u32(&smA[b][lrow * 40 + lhalf * 16]);
        const __nv_bfloat16* ga = pA + (size_t)(m0 + lrow) * K + kt + lhalf * 16;
        cpa16(da, ga); cpa16(da + 16, ga + 8);
        const uint32_t db = smem_u32(&smB[b][lrow * 40 + lhalf * 16]);
        const __nv_bfloat16* gb = pB + (size_t)(j0 + lrow) * K + kt + lhalf * 16;
        cpa16(db, gb); cpa16(db + 16, gb + 8);
    };

    copy_chunk(0, 0); CPA_COMMIT;
    copy_chunk(1, 1); CPA_COMMIT;

    for (int c = 0; c < NCH; c++) {
        if (c + 1 < NCH) { CPA_WAIT1; } else { CPA_WAIT0; }
        __syncthreads();

        const int cur = c & 1;
        const uint32_t baseA = smem_u32(&smA[cur][0]);
        const uint32_t baseB = smem_u32(&smB[cur][0]);
#pragma unroll
        for (int kk = 0; kk < 2; kk++) {
            uint32_t aF[2][4], bF[4][4];
#pragma unroll
            for (int mt = 0; mt < 2; mt++)
                ldmx4(aF[mt], baseA +
                      ((wm * 32 + mt * 16 + (lane & 15)) * 40 + kk * 16 + (lane >> 4) * 8) * 2);
#pragma unroll
            for (int np = 0; np < 4; np++)
                ldmx4(bF[np], baseB +
                      ((wn * 64 + np * 16 + (lane & 15)) * 40 + kk * 16 + (lane >> 4) * 8) * 2);
#pragma unroll
            for (int mt = 0; mt < 2; mt++)
#pragma unroll
                for (int np = 0; np < 4; np++) {
                    mma16816(acc[mt][2 * np + 0], aF[mt], bF[np][0], bF[np][2]);
                    mma16816(acc[mt][2 * np + 1], aF[mt], bF[np][1], bF[np][3]);
                }
        }
        __syncthreads();
        if (c + 2 < NCH) { copy_chunk(c + 2, cur); CPA_COMMIT; }
    }

    // epilogue
#pragma unroll
    for (int mt = 0; mt < 2; mt++) {
        const int rbase = m0 + wm * 32 + mt * 16 + (lane >> 2);
#pragma unroll
        for (int half = 0; half < 2; half++) {
            const int rm = rbase + half * 8;
            const int orow = (rm % D1) * D2 + rm / D1;
#pragma unroll
            for (int nt = 0; nt < 8; nt++) {
                const int cn = j0 + wn * 64 + nt * 8 + (lane & 3) * 2;
                float bb0 = b1[cn], bb1 = b1[cn + 1];
                if (b2) { bb0 += b2[cn]; bb1 += b2[cn + 1]; }
                float x = acc[mt][nt][2 * half + 0] + bb0;
                float y = acc[mt][nt][2 * half + 1] + bb1;
                if (act) { x = retanh(x); y = retanh(y); }
                const size_t oidx = (size_t)orow * Nc + cn;
                if (omode == 0) {
                    float2 v; v.x = x; v.y = y;
                    *(float2*)(C + oidx) = v;
                } else {
                    __nv_bfloat16 hx = __float2bfloat16(x);
                    __nv_bfloat16 hy = __float2bfloat16(y);
                    __nv_bfloat16 lx = __float2bfloat16(x - __bfloat162float(hx));
                    __nv_bfloat16 ly = __float2bfloat16(y - __bfloat162float(hy));
                    *(__nv_bfloat162*)(hiO + oidx) = __nv_bfloat162(hx, hy);
                    *(__nv_bfloat162*)(loO + oidx) = __nv_bfloat162(lx, ly);
                }
            }
        }
    }
}

// ======================= fp32 -> bf16 hi/lo split (inputs/weights only) =======
__global__ __launch_bounds__(256) void cvt_split(
    const float* __restrict__ x, __nv_bfloat16* __restrict__ hi,
    __nv_bfloat16* __restrict__ lo, int n4)
{
    const int i = blockIdx.x * 256 + threadIdx.x;
    if (i >= n4) return;
    const float4 v = ((const float4*)x)[i];
    __nv_bfloat16 h0 = __float2bfloat16(v.x), h1 = __float2bfloat16(v.y);
    __nv_bfloat16 h2 = __float2bfloat16(v.z), h3 = __float2bfloat16(v.w);
    __nv_bfloat16 l0 = __float2bfloat16(v.x - __bfloat162float(h0));
    __nv_bfloat16 l1 = __float2bfloat16(v.y - __bfloat162float(h1));
    __nv_bfloat16 l2 = __float2bfloat16(v.z - __bfloat162float(h2));
    __nv_bfloat16 l3 = __float2bfloat16(v.w - __bfloat162float(h3));
    ((__nv_bfloat162*)hi)[2 * i]     = __nv_bfloat162(h0, h1);
    ((__nv_bfloat162*)hi)[2 * i + 1] = __nv_bfloat162(h2, h3);
    ((__nv_bfloat162*)lo)[2 * i]     = __nv_bfloat162(l0, l1);
    ((__nv_bfloat162*)lo)[2 * i + 1] = __nv_bfloat162(l2, l3);
}

// ======================= helpers ==============================================
__global__ __launch_bounds__(512) void transpose_h0(
    const float* __restrict__ h0, float* __restrict__ hx)
{
    const int idx = blockIdx.x * 512 + threadIdx.x;
    hx[idx] = h0[(size_t)(idx & 63) * HH + (idx >> 6)];
}
__global__ __launch_bounds__(1024) void reset_flags_kernel() {
    g_gflag[threadIdx.x] = 0u;
}

// ======================= persistent recurrence (+ fused bf16 split out) =======
#define RGRID 128
#define RTHR  512
#define RSMEM ((16384 + 9216) * 4)

__global__ __launch_bounds__(RTHR) void recur_kernel(
    float* __restrict__ buf, const float* __restrict__ Wh,
    float* __restrict__ hx0, float* __restrict__ hx1,
    __nv_bfloat16* __restrict__ aHp, __nv_bfloat16* __restrict__ aLp)
{
    extern __shared__ float smem[];
    float* Whs = smem;                                                // [1024][16]
    unsigned long long* redU = (unsigned long long*)(smem + 16384);   // [16][32][9]

    const int tid  = threadIdx.x;
    const int bidb = blockIdx.x >> 6;
    const int bidh = blockIdx.x & 63;
    const int nb0  = bidb * 32;
    const int c0   = bidh * 16;

    {
        const int cl = tid & 15;
        const int kb = (tid >> 4) * 32;
        const float* wrow = Wh + (size_t)(c0 + cl) * HH + kb;
#pragma unroll
        for (int kk = 0; kk < 32; kk++) Whs[(kb + kk) * 16 + cl] = wrow[kk];
    }
    __syncthreads();

    const int wid  = tid >> 5;
    const int lane = tid & 31;
    const int k0   = wid * 64;
    const int cR   = lane & 15;
    const int nR   = 2 * wid + (lane >> 4);
    const float* redF = (const float*)redU;

    const unsigned* wf = &g_gflag[(bidb * 16 + wid) * 32];
    unsigned* pf = &g_gflag[(bidb * 16 + (bidh >> 2)) * 32];

    for (int t = 0; t < TT; t++) {
        const float* hp = ((t & 1) ? hx1 : hx0) + (size_t)k0 * NB + nb0 + lane;
        float*       hn = ((t & 1) ? hx0 : hx1);
        const size_t oidx = (size_t)t * NHh + (size_t)(nb0 + nR) * HH + (c0 + cR);
        float* outp = buf + oidx;
        const float x_pre = __ldcg(outp);
        {
            const unsigned tgt = 4u * (unsigned)t;
            while (ld_acq(wf) < tgt) __nanosleep(20);
        }
        unsigned long long acc[8];
#pragma unroll
        for (int j = 0; j < 8; j++) acc[j] = 0ull;
        float hbuf[3][8];
#pragma unroll
        for (int j = 0; j < 8; j++) hbuf[0][j] = __ldcg(hp + (size_t)j * NB);
#pragma unroll
        for (int j = 0; j < 8; j++) hbuf[1][j] = __ldcg(hp + (size_t)(8 + j) * NB);
#pragma unroll
        for (int g = 0; g < 8; g++) {
            if (g + 2 < 8) {
#pragma unroll
                for (int j = 0; j < 8; j++)
                    hbuf[(g + 2) % 3][j] = __ldcg(hp + (size_t)((g + 2) * 8 + j) * NB);
            }
#pragma unroll
            for (int j = 0; j < 8; j++) {
                const unsigned long long ad = dup2(hbuf[g % 3][j]);
                const float* wk = &Whs[(k0 + g * 8 + j) * 16];
                ulonglong2 w0 = *(const ulonglong2*)(wk + 0);
                ulonglong2 w1 = *(const ulonglong2*)(wk + 4);
                ulonglong2 w2 = *(const ulonglong2*)(wk + 8);
                ulonglong2 w3 = *(const ulonglong2*)(wk + 12);
                fma2(acc[0], ad, w0.x); fma2(acc[1], ad, w0.y);
                fma2(acc[2], ad, w1.x); fma2(acc[3], ad, w1.y);
                fma2(acc[4], ad, w2.x); fma2(acc[5], ad, w2.y);
                fma2(acc[6], ad, w3.x); fma2(acc[7], ad, w3.y);
            }
        }
        {
            unsigned long long* rp = &redU[(size_t)(wid * 32 + lane) * 9];
#pragma unroll
            for (int j = 0; j < 8; j++) rp[j] = acc[j];
        }
        __syncthreads();
        float s = 0.0f;
#pragma unroll
        for (int w = 0; w < 16; w++) s += redF[(w * 32 + nR) * 18 + cR];
        const float v = retanh(s + x_pre);
        *outp = v;                                   // fp32 (unused downstream ok)
        {                                            // fused bf16 hi/lo for GEMMs
            __nv_bfloat16 hv = __float2bfloat16(v);
            aHp[oidx] = hv;
            aLp[oidx] = __float2bfloat16(v - __bfloat162float(hv));
        }
        hn[(size_t)(c0 + cR) * NB + nb0 + nR] = v;   // [H][N] for next step
        __syncthreads();
        if (tid == 0) red_rel(pf, 1u);
    }
}

// ======================= launcher ==============================================
static void cvt(const float* x, __nv_bfloat16* hi, __nv_bfloat16* lo, int n) {
    cvt_split<<<(n / 4 + 255) / 256, 256>>>(x, hi, lo, n / 4);
}

extern "C" void kernel_launch(void* const* d_in, const int* in_sizes, int n_in,
                              void* d_out, int out_size)
{
    const float* data = (const float*)d_in[0];
    const float* h0_v = (const float*)d_in[1];
    const float* h0_m = (const float*)d_in[2];
    const float* Wi   = (const float*)d_in[3];
    const float* bi   = (const float*)d_in[4];
    const float* Wh   = (const float*)d_in[5];
    const float* bh   = (const float*)d_in[6];
    const float* Wo   = (const float*)d_in[7];
    const float* bo   = (const float*)d_in[8];
    const float* Wt   = (const float*)d_in[9];
    const float* bt   = (const float*)d_in[10];
    const float* Wi2  = (const float*)d_in[11];
    const float* bi2  = (const float*)d_in[12];
    const float* Wh2  = (const float*)d_in[13];
    const float* bh2  = (const float*)d_in[14];
    const float* Wo2  = (const float*)d_in[15];
    const float* bo2  = (const float*)d_in[16];
    float* out = (float*)d_out;

    float *bufA, *bufB, *hx0, *hx1;
    cudaGetSymbolAddress((void**)&bufA, g_bufA);
    cudaGetSymbolAddress((void**)&bufB, g_bufB);
    cudaGetSymbolAddress((void**)&hx0,  g_hx0);
    cudaGetSymbolAddress((void**)&hx1,  g_hx1);
    __nv_bfloat16 *dH,*dL,*aH,*aL,*oH,*oL,*o2H,*o2L;
    __nv_bfloat16 *WiH,*WiL,*WoH,*WoL,*WtH,*WtL,*Wi2H,*Wi2L,*Wo2H,*Wo2L;
    cudaGetSymbolAddress((void**)&dH, g_dHi);   cudaGetSymbolAddress((void**)&dL, g_dLo);
    cudaGetSymbolAddress((void**)&aH, g_aHi);   cudaGetSymbolAddress((void**)&aL, g_aLo);
    cudaGetSymbolAddress((void**)&oH, g_oHi);   cudaGetSymbolAddress((void**)&oL, g_oLo);
    cudaGetSymbolAddress((void**)&o2H, g_o2Hi); cudaGetSymbolAddress((void**)&o2L, g_o2Lo);
    cudaGetSymbolAddress((void**)&WiH, g_WiH);  cudaGetSymbolAddress((void**)&WiL, g_WiL);
    cudaGetSymbolAddress((void**)&WoH, g_WoH);  cudaGetSymbolAddress((void**)&WoL, g_WoL);
    cudaGetSymbolAddress((void**)&WtH, g_WtH);  cudaGetSymbolAddress((void**)&WtL, g_WtL);
    cudaGetSymbolAddress((void**)&Wi2H, g_Wi2H); cudaGetSymbolAddress((void**)&Wi2L, g_Wi2L);
    cudaGetSymbolAddress((void**)&Wo2H, g_Wo2H); cudaGetSymbolAddress((void**)&Wo2L, g_Wo2L);

    cudaFuncSetAttribute(recur_kernel,
                         cudaFuncAttributeMaxDynamicSharedMemorySize, RSMEM);

    // weight + data converts (inputs only; all intermediates fused)
    cvt(Wi,  WiH,  WiL,  HH * II);
    cvt(Wo,  WoH,  WoL,  OO * HH);
    cvt(Wt,  WtH,  WtL,  OO * OO);
    cvt(Wi2, Wi2H, Wi2L, HH * OO);
    cvt(Wo2, Wo2H, Wo2L, OO * HH);
    cvt(data, dH, dL, NT * II);

    // G1: inp_v = data @ Wi^T + (bi+bh) -> fp32 [T,N,H]
    hgemm<<<dim3(HH / 128, NT / 128), 256>>>(
        dH, dL, WiH, WiL, bi, bh, bufA, nullptr, nullptr, II, HH, TT, NB, 0, 0);
    // visual recurrence (writes hs_v fp32 + bf16 hi/lo)
    transpose_h0<<<128, 512>>>(h0_v, hx0);
    reset_flags_kernel<<<1, 1024>>>();
    recur_kernel<<<RGRID, RTHR, RSMEM>>>(bufA, Wh, hx0, hx1, aH, aL);
    // G3: out_v = hs_v @ Wo^T + bo -> bf16 split [N,T,O]
    hgemm<<<dim3(OO / 128, NT / 128), 256>>>(
        aH, aL, WoH, WoL, bo, nullptr, nullptr, oH, oL, HH, OO, NB, TT, 0, 1);
    // G4: out_t = retanh(out_v @ Wt^T + bt) -> bf16 split [N,T,O]
    hgemm<<<dim3(OO / 128, NT / 128), 256>>>(
        oH, oL, WtH, WtL, bt, nullptr, nullptr, o2H, o2L, OO, OO, NT, 1, 1, 1);
    // G5: inp_m = out_t @ Wi2^T + (bi2+bh2) -> fp32 [T,N,H]
    hgemm<<<dim3(HH / 128, NT / 128), 256>>>(
        o2H, o2L, Wi2H, Wi2L, bi2, bh2, bufB, nullptr, nullptr, OO, HH, TT, NB, 0, 0);
    // motor recurrence (writes hs_m bf16 hi/lo into aH/aL)
    transpose_h0<<<128, 512>>>(h0_m, hx0);
    reset_flags_kernel<<<1, 1024>>>();
    recur_kernel<<<RGRID, RTHR, RSMEM>>>(bufB, Wh2, hx0, hx1, aH, aL);
    // G7: out_m = hs_m @ Wo2^T + bo2 -> fp32 [N,T,O]
    hgemm<<<dim3(OO / 128, NT / 128), 256>>>(
        aH, aL, Wo2H, Wo2L, bo2, nullptr, out, nullptr, nullptr, HH, OO, NB, TT, 0, 0);
}